// round 14
// baseline (speedup 1.0000x reference)
#include <cuda_runtime.h>
#include <cstdint>

#define NBLK 24
#define BATCH 256
#define CH 32
#define TQ 256
#define TQO 257

#define NROWS   (NBLK * BATCH * CH)
#define NELEM   (NROWS * TQ)                // 50,331,648 floats
#define NELEM4  (NELEM / 4)                 // 12,582,912 float4

#define CMP_CTAS 64
#define PURE_COPY_CTAS 160
#define GRID (CMP_CTAS + PURE_COPY_CTAS)    // 224
#define TPB 256

#define COPY_THREADS 49152                  // 64*128 + 160*256
#define COPY_PER_THR (NELEM4 / COPY_THREADS)// 256 float4 per thread, exact
#define COPY_UNROLL 16
#define COPY_ITERS  (COPY_PER_THR / COPY_UNROLL)  // 16 exact

// Dynamic smem layout (float offsets)
#define WC_OFF   0              // [2][4096]  W_conv interleaved (o,c,k), swizzled
#define WRS_OFF  8192           // [2][1024]
#define WSK_OFF  10240          // [2][1024]
#define WO1_OFF  12288          // [2][4096]
#define ACT_OFF  20480          // tap[4][32] | cur[4][32] | g[4][32]
#define SMEM_FLOATS (ACT_OFF + 384)
#define SMEM_BYTES  (SMEM_FLOATS * 4)       // 83456 B -> 2 CTAs/SM

// Swizzles: XOR 16B-chunk index with (row & 7) -> conflict-free per 8-lane phase.
#define SWZ16(o, p) (((o) << 6) + ((((p) ^ ((o) & 7)) << 2)))   // 64-float rows
#define SWZ8(r, q)  (((r) << 5) + ((((q) ^ ((r) & 7)) << 2)))   // 32-float rows

__device__ __forceinline__ void cpa16(unsigned int dst_smem, const void* src) {
    asm volatile("cp.async.cg.shared.global [%0], [%1], 16;\n"
                 :: "r"(dst_smem), "l"(src));
}
__device__ __forceinline__ void cpa_commit() {
    asm volatile("cp.async.commit_group;\n" ::: "memory");
}
__device__ __forceinline__ void cpa_wait0() {
    asm volatile("cp.async.wait_group 0;\n" ::: "memory");
}
__device__ __forceinline__ void cmp_bar() {   // compute sub-block barrier (128 thr)
    asm volatile("bar.sync 1, 128;" ::: "memory");
}

// ---------------------------------------------------------------------------
// Fused kernel, warp-specialized:
//   CTA < 64 : tid<128 -> compute warps (R11 pipeline, named barrier)
//              tid>=128 -> copy warps
//   CTA >= 64: all 8 warps copy
// One wave (224 CTAs, 2/SM) => guaranteed overlap.
// ---------------------------------------------------------------------------
__global__ void __launch_bounds__(TPB, 2) wave_fused_kernel(
    const float* __restrict__ queues,
    const float* __restrict__ x,
    const float* __restrict__ num,
    const int*   __restrict__ cat,
    const float* __restrict__ emb,
    const float* __restrict__ W_in,
    const float* __restrict__ b_in,
    const float* __restrict__ W_conv,   // (24,64,32,2)
    const float* __restrict__ b_conv,
    const float* __restrict__ W_res,    // (24,32,32)
    const float* __restrict__ b_res,
    const float* __restrict__ W_skip,   // (24,32,32)
    const float* __restrict__ b_skip,
    const float* __restrict__ W_o1,     // (128,768)
    const float* __restrict__ b_o1,
    const float* __restrict__ W_o2,
    const float* __restrict__ b_o2,
    float* __restrict__ out)
{
    extern __shared__ __align__(16) float sm[];
    float* __restrict__ nq = out + BATCH;
    const int tid = threadIdx.x;
    const int cta = blockIdx.x;

    unsigned ci;
    bool is_copy;
    if (cta < CMP_CTAS) {
        is_copy = (tid >= 128);
        ci = cta * 128u + (unsigned)(tid - 128);
    } else {
        is_copy = true;
        ci = CMP_CTAS * 128u + (cta - CMP_CTAS) * 256u + (unsigned)tid;
    }

    if (is_copy) {
        // ---------------- COPY ROLE ----------------------------------------
        const float4* __restrict__ s4 = (const float4*)queues;
        unsigned idx4 = ci;
#pragma unroll 1
        for (int it = 0; it < COPY_ITERS; it++) {
            float4 v[COPY_UNROLL];
#pragma unroll
            for (int j = 0; j < COPY_UNROLL; j++)
                v[j] = __ldcs(&s4[idx4 + j * COPY_THREADS]);
#pragma unroll
            for (int j = 0; j < COPY_UNROLL; j++) {
                const unsigned i4 = idx4 + j * COPY_THREADS;
                float* p = nq + 4u * i4 + (i4 >> 6);   // 4*i4 + (4*i4)>>8
                __stcs(p,     v[j].x);
                __stcs(p + 1, v[j].y);
                __stcs(p + 2, v[j].z);
                __stcs(p + 3, v[j].w);
            }
            idx4 += COPY_UNROLL * COPY_THREADS;
        }
        return;
    }

    // ---------------- COMPUTE ROLE (tid 0..127; R11 pipeline) --------------
    const int w    = tid >> 5;
    const int lane = tid & 31;
    const int b    = cta * 4 + w;

    const unsigned int smem_u32 = (unsigned int)__cvta_generic_to_shared(sm);

    float* s_tap = sm + ACT_OFF       + w * 32;
    float* s_cur = sm + ACT_OFF + 128 + w * 32;
    float* s_g   = sm + ACT_OFF + 256 + w * 32;

    auto issue_stage = [&](int blk, int beta) {
#pragma unroll
        for (int j = 0; j < 8; j++) {
            const int m = tid + j * 128;          // 0..1023
            const int o = m >> 4, ch = m & 15;
            cpa16(smem_u32 + (WC_OFF + beta * 4096 + SWZ16(o, ch)) * 4,
                  W_conv + (size_t)blk * 4096 + m * 4);
        }
#pragma unroll
        for (int j = 0; j < 2; j++) {
            const int m = tid + j * 128;          // 0..255
            const int o = m >> 3, ch = m & 7;
            cpa16(smem_u32 + (WRS_OFF + beta * 1024 + SWZ8(o, ch)) * 4,
                  W_res + (size_t)blk * 1024 + m * 4);
            cpa16(smem_u32 + (WSK_OFF + beta * 1024 + SWZ8(o, ch)) * 4,
                  W_skip + (size_t)blk * 1024 + m * 4);
        }
#pragma unroll
        for (int j = 0; j < 8; j++) {
            const int m = tid + j * 128;          // 0..1023
            const int h = m >> 3, ch = m & 7;
            cpa16(smem_u32 + (WO1_OFF + beta * 4096 + SWZ8(h, ch)) * 4,
                  W_o1 + (size_t)h * 768 + blk * 32 + ch * 4);
        }
        cpa_commit();
    };

    issue_stage(0, 0);

    float zb0  = b_conv[lane];
    float zb1  = b_conv[32 + lane];
    float rb   = b_res [lane];
    float sb   = b_skip[lane];
    float tapc = queues[((size_t)b * CH + lane) * TQ + (TQ - 1)];

    if (lane < 25) {
        float v;
        if (lane == 0)      v = x[b];
        else if (lane < 9)  v = num[b * 8 + (lane - 1)];
        else                v = emb[cat[b] * 16 + (lane - 9)];
        s_g[lane] = v;
    }
    __syncwarp();
    float cur = b_in[lane];
#pragma unroll
    for (int k = 0; k < 25; k++)
        cur += W_in[lane * 25 + k] * s_g[k];
    __syncwarp();

    float acc0 = 0.f, acc1 = 0.f, acc2 = 0.f, acc3 = 0.f;

#pragma unroll 1
    for (int i = 0; i < NBLK; i++) {
        const int alpha = i & 1;

        cpa_wait0();
        cmp_bar();

        if (i < NBLK - 1)
            issue_stage(i + 1, alpha ^ 1);

        float zb0n, zb1n, rbn, sbn, tapn;
        if (i < NBLK - 1) {
            const int in = i + 1;
            zb0n = b_conv[in * 64 + lane];
            zb1n = b_conv[in * 64 + 32 + lane];
            rbn  = b_res [in * 32 + lane];
            sbn  = b_skip[in * 32 + lane];
            const int dn = 1 << (in & 7);
            tapn = queues[((size_t)(in * BATCH + b) * CH + lane) * TQ + (TQ - dn)];
        }

        const size_t rowbase = (size_t)(i * BATCH + b) * CH + lane;
        nq[rowbase * TQO + TQ] = cur;
        s_tap[lane] = tapc;
        s_cur[lane] = cur;
        __syncwarp();

        const float* wc  = sm + WC_OFF  + alpha * 4096;
        const float* wrs = sm + WRS_OFF + alpha * 1024;
        const float* wsk = sm + WSK_OFF + alpha * 1024;
        const float* wo1 = sm + WO1_OFF + alpha * 4096;

        float z0a = zb0, z0b = 0.f, z1a = zb1, z1b = 0.f;
#pragma unroll
        for (int q = 0; q < 8; q++) {
            const float4 a  = *(const float4*)&s_tap[4 * q];
            const float4 u  = *(const float4*)&s_cur[4 * q];
            const float4 f00 = *(const float4*)&wc[SWZ16(lane,      2 * q    )];
            const float4 f01 = *(const float4*)&wc[SWZ16(lane,      2 * q + 1)];
            const float4 f10 = *(const float4*)&wc[SWZ16(lane + 32, 2 * q    )];
            const float4 f11 = *(const float4*)&wc[SWZ16(lane + 32, 2 * q + 1)];
            z0a += a.x * f00.x + a.y * f00.z;
            z0b += u.x * f00.y + u.y * f00.w;
            z0a += a.z * f01.x + a.w * f01.z;
            z0b += u.z * f01.y + u.w * f01.w;
            z1a += a.x * f10.x + a.y * f10.z;
            z1b += u.x * f10.y + u.y * f10.w;
            z1a += a.z * f11.x + a.w * f11.z;
            z1b += u.z * f11.y + u.w * f11.w;
        }

        const float z1s = z1a + z1b;
        const float gated = tanhf(z0a + z0b) * (1.f / (1.f + __expf(-z1s)));
        s_g[lane] = gated;
        __syncwarp();

        float sk = sb, rs = rb;
#pragma unroll
        for (int q = 0; q < 8; q++) {
            const float4 g  = *(const float4*)&s_g[4 * q];
            const float4 wr = *(const float4*)&wrs[SWZ8(lane, q)];
            const float4 ws = *(const float4*)&wsk[SWZ8(lane, q)];
            rs += g.x * wr.x + g.y * wr.y + g.z * wr.z + g.w * wr.w;
            sk += g.x * ws.x + g.y * ws.y + g.z * ws.z + g.w * ws.w;
        }
        cur = rs + cur;

        s_tap[lane] = fmaxf(sk, 0.f);
        __syncwarp();

#pragma unroll
        for (int q = 0; q < 8; q++) {
            const float4 sr = *(const float4*)&s_tap[4 * q];
            const float4 v0 = *(const float4*)&wo1[SWZ8(lane,      q)];
            const float4 v1 = *(const float4*)&wo1[SWZ8(lane + 32, q)];
            const float4 v2 = *(const float4*)&wo1[SWZ8(lane + 64, q)];
            const float4 v3 = *(const float4*)&wo1[SWZ8(lane + 96, q)];
            acc0 += sr.x * v0.x + sr.y * v0.y + sr.z * v0.z + sr.w * v0.w;
            acc1 += sr.x * v1.x + sr.y * v1.y + sr.z * v1.z + sr.w * v1.w;
            acc2 += sr.x * v2.x + sr.y * v2.y + sr.z * v2.z + sr.w * v2.w;
            acc3 += sr.x * v3.x + sr.y * v3.y + sr.z * v3.z + sr.w * v3.w;
        }

        if (i < NBLK - 1) {
            zb0 = zb0n; zb1 = zb1n; rb = rbn; sb = sbn; tapc = tapn;
        }
        cmp_bar();
    }

    float p = 0.f;
    p += fmaxf(acc0 + b_o1[lane      ], 0.f) * W_o2[lane      ];
    p += fmaxf(acc1 + b_o1[lane + 32 ], 0.f) * W_o2[lane + 32 ];
    p += fmaxf(acc2 + b_o1[lane + 64 ], 0.f) * W_o2[lane + 64 ];
    p += fmaxf(acc3 + b_o1[lane + 96 ], 0.f) * W_o2[lane + 96 ];
#pragma unroll
    for (int off = 16; off; off >>= 1)
        p += __shfl_xor_sync(0xffffffffu, p, off);
    if (lane == 0)
        out[b] = p + b_o2[0];
}

extern "C" void kernel_launch(void* const* d_in, const int* in_sizes, int n_in,
                              void* d_out, int out_size) {
    const float* queues = (const float*)d_in[0];
    const float* x      = (const float*)d_in[1];
    const float* num    = (const float*)d_in[2];
    const int*   cat    = (const int*)  d_in[3];
    const float* emb    = (const float*)d_in[4];
    const float* W_in   = (const float*)d_in[5];
    const float* b_in   = (const float*)d_in[6];
    const float* W_conv = (const float*)d_in[7];
    const float* b_conv = (const float*)d_in[8];
    const float* W_res  = (const float*)d_in[9];
    const float* b_res  = (const float*)d_in[10];
    const float* W_skip = (const float*)d_in[11];
    const float* b_skip = (const float*)d_in[12];
    const float* W_o1   = (const float*)d_in[13];
    const float* b_o1   = (const float*)d_in[14];
    const float* W_o2   = (const float*)d_in[15];
    const float* b_o2   = (const float*)d_in[16];
    float* out = (float*)d_out;

    static bool configured = false;
    if (!configured) {
        configured = true;
        cudaFuncSetAttribute(wave_fused_kernel,
                             cudaFuncAttributeMaxDynamicSharedMemorySize,
                             SMEM_BYTES);
    }

    wave_fused_kernel<<<GRID, TPB, SMEM_BYTES>>>(
        queues, x, num, cat, emb, W_in, b_in, W_conv, b_conv,
        W_res, b_res, W_skip, b_skip, W_o1, b_o1, W_o2, b_o2, out);
}

// round 15
// speedup vs baseline: 1.4248x; 1.4248x over previous
#include <cuda_runtime.h>
#include <cstdint>

#define NBLK 24
#define BATCH 256
#define CH 32
#define TQ 256
#define TQO 257

#define NROWS   (NBLK * BATCH * CH)         // 196608 rows of 256 floats

#define CMP_CTAS 64
#define COPY_CTAS 192
#define TPB 128

#define COPY_WARPS (COPY_CTAS * 4)          // 768
#define ROWS_PER_IT 4
#define COPY_ITERS (NROWS / (COPY_WARPS * ROWS_PER_IT))  // 64 exact

// Dynamic smem layout (float offsets)
#define WC_OFF   0              // [2][4096]  W_conv interleaved (o,c,k), swizzled
#define WRS_OFF  8192           // [2][1024]
#define WSK_OFF  10240          // [2][1024]
#define WO1_OFF  12288          // [2][4096]
#define ACT_OFF  20480          // tap[4][32] | cur[4][32] | g[4][32]
#define SMEM_FLOATS (ACT_OFF + 384)
#define SMEM_BYTES  (SMEM_FLOATS * 4)       // 83456 B -> 2 CTAs/SM

// Swizzles: XOR 16B-chunk index with (row & 7) -> conflict-free per 8-lane phase.
#define SWZ16(o, p) (((o) << 6) + ((((p) ^ ((o) & 7)) << 2)))   // 64-float rows
#define SWZ8(r, q)  (((r) << 5) + ((((q) ^ ((r) & 7)) << 2)))   // 32-float rows

__device__ __forceinline__ void cpa16(unsigned int dst_smem, const void* src) {
    asm volatile("cp.async.cg.shared.global [%0], [%1], 16;\n"
                 :: "r"(dst_smem), "l"(src));
}
__device__ __forceinline__ void cpa_commit() {
    asm volatile("cp.async.commit_group;\n" ::: "memory");
}
__device__ __forceinline__ void cpa_wait0() {
    asm volatile("cp.async.wait_group 0;\n" ::: "memory");
}

// ---------------------------------------------------------------------------
// Fused kernel: blockIdx < CMP_CTAS -> recurrent compute; else queue copy.
// Single grid (256 CTAs, 2/SM smem limit) => one wave, guaranteed overlap.
// Copy role: warp-per-row, lane-stride-4B loads AND stores (every LDG.32 /
// STG.32 is one fully-utilized 128B transaction); 4 rows per iteration for
// MLP=32 per warp.
// ---------------------------------------------------------------------------
__global__ void __launch_bounds__(TPB) wave_fused_kernel(
    const float* __restrict__ queues,
    const float* __restrict__ x,
    const float* __restrict__ num,
    const int*   __restrict__ cat,
    const float* __restrict__ emb,
    const float* __restrict__ W_in,
    const float* __restrict__ b_in,
    const float* __restrict__ W_conv,   // (24,64,32,2)
    const float* __restrict__ b_conv,
    const float* __restrict__ W_res,    // (24,32,32)
    const float* __restrict__ b_res,
    const float* __restrict__ W_skip,   // (24,32,32)
    const float* __restrict__ b_skip,
    const float* __restrict__ W_o1,     // (128,768)
    const float* __restrict__ b_o1,
    const float* __restrict__ W_o2,
    const float* __restrict__ b_o2,
    float* __restrict__ out)
{
    extern __shared__ __align__(16) float sm[];
    float* __restrict__ nq = out + BATCH;
    const int tid = threadIdx.x;

    if (blockIdx.x >= CMP_CTAS) {
        // ---------------- COPY ROLE: warp-per-row, 4 rows/iter --------------
        const int lane = tid & 31;
        const int gw   = (blockIdx.x - CMP_CTAS) * 4 + (tid >> 5);  // 0..767
        int row = gw * ROWS_PER_IT;
#pragma unroll 1
        for (int it = 0; it < COPY_ITERS; it++) {
            float v[ROWS_PER_IT][8];
#pragma unroll
            for (int r = 0; r < ROWS_PER_IT; r++) {
                const float* src = queues + (size_t)(row + r) * TQ + lane;
#pragma unroll
                for (int k = 0; k < 8; k++)
                    v[r][k] = __ldcs(src + k * 32);
            }
#pragma unroll
            for (int r = 0; r < ROWS_PER_IT; r++) {
                float* dst = nq + (size_t)(row + r) * TQO + lane;
#pragma unroll
                for (int k = 0; k < 8; k++)
                    __stcs(dst + k * 32, v[r][k]);
            }
            row += COPY_WARPS * ROWS_PER_IT;
        }
        return;
    }

    // ---------------- COMPUTE ROLE (R11/R13 pipeline, unchanged) -----------
    const int w    = tid >> 5;
    const int lane = tid & 31;
    const int b    = blockIdx.x * 4 + w;

    const unsigned int smem_u32 = (unsigned int)__cvta_generic_to_shared(sm);

    float* s_tap = sm + ACT_OFF       + w * 32;
    float* s_cur = sm + ACT_OFF + 128 + w * 32;
    float* s_g   = sm + ACT_OFF + 256 + w * 32;

    auto issue_stage = [&](int blk, int beta) {
#pragma unroll
        for (int j = 0; j < 8; j++) {
            const int m = tid + j * 128;          // 0..1023
            const int o = m >> 4, ch = m & 15;
            cpa16(smem_u32 + (WC_OFF + beta * 4096 + SWZ16(o, ch)) * 4,
                  W_conv + (size_t)blk * 4096 + m * 4);
        }
#pragma unroll
        for (int j = 0; j < 2; j++) {
            const int m = tid + j * 128;          // 0..255
            const int o = m >> 3, ch = m & 7;
            cpa16(smem_u32 + (WRS_OFF + beta * 1024 + SWZ8(o, ch)) * 4,
                  W_res + (size_t)blk * 1024 + m * 4);
            cpa16(smem_u32 + (WSK_OFF + beta * 1024 + SWZ8(o, ch)) * 4,
                  W_skip + (size_t)blk * 1024 + m * 4);
        }
#pragma unroll
        for (int j = 0; j < 8; j++) {
            const int m = tid + j * 128;          // 0..1023
            const int h = m >> 3, ch = m & 7;
            cpa16(smem_u32 + (WO1_OFF + beta * 4096 + SWZ8(h, ch)) * 4,
                  W_o1 + (size_t)h * 768 + blk * 32 + ch * 4);
        }
        cpa_commit();
    };

    issue_stage(0, 0);

    float zb0  = b_conv[lane];
    float zb1  = b_conv[32 + lane];
    float rb   = b_res [lane];
    float sb   = b_skip[lane];
    float tapc = queues[((size_t)b * CH + lane) * TQ + (TQ - 1)];

    if (lane < 25) {
        float v;
        if (lane == 0)      v = x[b];
        else if (lane < 9)  v = num[b * 8 + (lane - 1)];
        else                v = emb[cat[b] * 16 + (lane - 9)];
        s_g[lane] = v;
    }
    __syncwarp();
    float cur = b_in[lane];
#pragma unroll
    for (int k = 0; k < 25; k++)
        cur += W_in[lane * 25 + k] * s_g[k];
    __syncwarp();

    float acc0 = 0.f, acc1 = 0.f, acc2 = 0.f, acc3 = 0.f;

#pragma unroll 1
    for (int i = 0; i < NBLK; i++) {
        const int alpha = i & 1;

        cpa_wait0();
        __syncthreads();

        if (i < NBLK - 1)
            issue_stage(i + 1, alpha ^ 1);

        float zb0n, zb1n, rbn, sbn, tapn;
        if (i < NBLK - 1) {
            const int in = i + 1;
            zb0n = b_conv[in * 64 + lane];
            zb1n = b_conv[in * 64 + 32 + lane];
            rbn  = b_res [in * 32 + lane];
            sbn  = b_skip[in * 32 + lane];
            const int dn = 1 << (in & 7);
            tapn = queues[((size_t)(in * BATCH + b) * CH + lane) * TQ + (TQ - dn)];
        }

        const size_t rowbase = (size_t)(i * BATCH + b) * CH + lane;
        nq[rowbase * TQO + TQ] = cur;
        s_tap[lane] = tapc;
        s_cur[lane] = cur;
        __syncwarp();

        const float* wc  = sm + WC_OFF  + alpha * 4096;
        const float* wrs = sm + WRS_OFF + alpha * 1024;
        const float* wsk = sm + WSK_OFF + alpha * 1024;
        const float* wo1 = sm + WO1_OFF + alpha * 4096;

        float z0a = zb0, z0b = 0.f, z1a = zb1, z1b = 0.f;
#pragma unroll
        for (int q = 0; q < 8; q++) {
            const float4 a  = *(const float4*)&s_tap[4 * q];
            const float4 u  = *(const float4*)&s_cur[4 * q];
            const float4 f00 = *(const float4*)&wc[SWZ16(lane,      2 * q    )];
            const float4 f01 = *(const float4*)&wc[SWZ16(lane,      2 * q + 1)];
            const float4 f10 = *(const float4*)&wc[SWZ16(lane + 32, 2 * q    )];
            const float4 f11 = *(const float4*)&wc[SWZ16(lane + 32, 2 * q + 1)];
            z0a += a.x * f00.x + a.y * f00.z;
            z0b += u.x * f00.y + u.y * f00.w;
            z0a += a.z * f01.x + a.w * f01.z;
            z0b += u.z * f01.y + u.w * f01.w;
            z1a += a.x * f10.x + a.y * f10.z;
            z1b += u.x * f10.y + u.y * f10.w;
            z1a += a.z * f11.x + a.w * f11.z;
            z1b += u.z * f11.y + u.w * f11.w;
        }

        const float z1s = z1a + z1b;
        const float gated = tanhf(z0a + z0b) * (1.f / (1.f + __expf(-z1s)));
        s_g[lane] = gated;
        __syncwarp();

        float sk = sb, rs = rb;
#pragma unroll
        for (int q = 0; q < 8; q++) {
            const float4 g  = *(const float4*)&s_g[4 * q];
            const float4 wr = *(const float4*)&wrs[SWZ8(lane, q)];
            const float4 ws = *(const float4*)&wsk[SWZ8(lane, q)];
            rs += g.x * wr.x + g.y * wr.y + g.z * wr.z + g.w * wr.w;
            sk += g.x * ws.x + g.y * ws.y + g.z * ws.z + g.w * ws.w;
        }
        cur = rs + cur;

        s_tap[lane] = fmaxf(sk, 0.f);
        __syncwarp();

#pragma unroll
        for (int q = 0; q < 8; q++) {
            const float4 sr = *(const float4*)&s_tap[4 * q];
            const float4 v0 = *(const float4*)&wo1[SWZ8(lane,      q)];
            const float4 v1 = *(const float4*)&wo1[SWZ8(lane + 32, q)];
            const float4 v2 = *(const float4*)&wo1[SWZ8(lane + 64, q)];
            const float4 v3 = *(const float4*)&wo1[SWZ8(lane + 96, q)];
            acc0 += sr.x * v0.x + sr.y * v0.y + sr.z * v0.z + sr.w * v0.w;
            acc1 += sr.x * v1.x + sr.y * v1.y + sr.z * v1.z + sr.w * v1.w;
            acc2 += sr.x * v2.x + sr.y * v2.y + sr.z * v2.z + sr.w * v2.w;
            acc3 += sr.x * v3.x + sr.y * v3.y + sr.z * v3.z + sr.w * v3.w;
        }

        if (i < NBLK - 1) {
            zb0 = zb0n; zb1 = zb1n; rb = rbn; sb = sbn; tapc = tapn;
        }
        __syncthreads();
    }

    float p = 0.f;
    p += fmaxf(acc0 + b_o1[lane      ], 0.f) * W_o2[lane      ];
    p += fmaxf(acc1 + b_o1[lane + 32 ], 0.f) * W_o2[lane + 32 ];
    p += fmaxf(acc2 + b_o1[lane + 64 ], 0.f) * W_o2[lane + 64 ];
    p += fmaxf(acc3 + b_o1[lane + 96 ], 0.f) * W_o2[lane + 96 ];
#pragma unroll
    for (int off = 16; off; off >>= 1)
        p += __shfl_xor_sync(0xffffffffu, p, off);
    if (lane == 0)
        out[b] = p + b_o2[0];
}

extern "C" void kernel_launch(void* const* d_in, const int* in_sizes, int n_in,
                              void* d_out, int out_size) {
    const float* queues = (const float*)d_in[0];
    const float* x      = (const float*)d_in[1];
    const float* num    = (const float*)d_in[2];
    const int*   cat    = (const int*)  d_in[3];
    const float* emb    = (const float*)d_in[4];
    const float* W_in   = (const float*)d_in[5];
    const float* b_in   = (const float*)d_in[6];
    const float* W_conv = (const float*)d_in[7];
    const float* b_conv = (const float*)d_in[8];
    const float* W_res  = (const float*)d_in[9];
    const float* b_res  = (const float*)d_in[10];
    const float* W_skip = (const float*)d_in[11];
    const float* b_skip = (const float*)d_in[12];
    const float* W_o1   = (const float*)d_in[13];
    const float* b_o1   = (const float*)d_in[14];
    const float* W_o2   = (const float*)d_in[15];
    const float* b_o2   = (const float*)d_in[16];
    float* out = (float*)d_out;

    static bool configured = false;
    if (!configured) {
        configured = true;
        cudaFuncSetAttribute(wave_fused_kernel,
                             cudaFuncAttributeMaxDynamicSharedMemorySize,
                             SMEM_BYTES);
    }

    wave_fused_kernel<<<CMP_CTAS + COPY_CTAS, TPB, SMEM_BYTES>>>(
        queues, x, num, cat, emb, W_in, b_in, W_conv, b_conv,
        W_res, b_res, W_skip, b_skip, W_o1, b_o1, W_o2, b_o2, out);
}

// round 16
// speedup vs baseline: 1.5233x; 1.0691x over previous
#include <cuda_runtime.h>
#include <cstdint>

#define NBLK 24
#define BATCH 256
#define CH 32
#define TQ 256
#define TQO 257

#define NROWS   (NBLK * BATCH * CH)         // 196608 rows of 256 floats

#define CMP_CTAS 64
#define COPY_CTAS 192
#define TPB 128

#define COPY_WARPS (COPY_CTAS * 4)          // 768
#define ROWS_PER_IT 8
#define COPY_ITERS (NROWS / (COPY_WARPS * ROWS_PER_IT))  // 32 exact

// Dynamic smem layout (float offsets)
#define WC_OFF   0              // [2][4096]  W_conv interleaved (o,c,k), swizzled
#define WRS_OFF  8192           // [2][1024]
#define WSK_OFF  10240          // [2][1024]
#define WO1_OFF  12288          // [2][4096]
#define ACT_OFF  20480          // tap[4][32] | cur[4][32] | g[4][32]
#define SMEM_FLOATS (ACT_OFF + 384)
#define SMEM_BYTES  (SMEM_FLOATS * 4)       // 83456 B -> 2 CTAs/SM

// Swizzles: XOR 16B-chunk index with (row & 7) -> conflict-free per 8-lane phase.
#define SWZ16(o, p) (((o) << 6) + ((((p) ^ ((o) & 7)) << 2)))   // 64-float rows
#define SWZ8(r, q)  (((r) << 5) + ((((q) ^ ((r) & 7)) << 2)))   // 32-float rows

__device__ __forceinline__ void cpa16(unsigned int dst_smem, const void* src) {
    asm volatile("cp.async.cg.shared.global [%0], [%1], 16;\n"
                 :: "r"(dst_smem), "l"(src));
}
__device__ __forceinline__ void cpa_commit() {
    asm volatile("cp.async.commit_group;\n" ::: "memory");
}
__device__ __forceinline__ void cpa_wait0() {
    asm volatile("cp.async.wait_group 0;\n" ::: "memory");
}

// ---------------------------------------------------------------------------
// Fused kernel: blockIdx < CMP_CTAS -> recurrent compute; else queue copy.
// Single grid (256 CTAs, 2/SM smem limit) => one wave, guaranteed overlap.
// Copy role: warp-per-row, lane-stride-4B loads AND stores (every LDG.32 /
// STG.32 is one fully-utilized 128B transaction); 8 rows per iteration for
// MLP=64 per warp (~42KB in flight per SM).
// ---------------------------------------------------------------------------
__global__ void __launch_bounds__(TPB) wave_fused_kernel(
    const float* __restrict__ queues,
    const float* __restrict__ x,
    const float* __restrict__ num,
    const int*   __restrict__ cat,
    const float* __restrict__ emb,
    const float* __restrict__ W_in,
    const float* __restrict__ b_in,
    const float* __restrict__ W_conv,   // (24,64,32,2)
    const float* __restrict__ b_conv,
    const float* __restrict__ W_res,    // (24,32,32)
    const float* __restrict__ b_res,
    const float* __restrict__ W_skip,   // (24,32,32)
    const float* __restrict__ b_skip,
    const float* __restrict__ W_o1,     // (128,768)
    const float* __restrict__ b_o1,
    const float* __restrict__ W_o2,
    const float* __restrict__ b_o2,
    float* __restrict__ out)
{
    extern __shared__ __align__(16) float sm[];
    float* __restrict__ nq = out + BATCH;
    const int tid = threadIdx.x;

    if (blockIdx.x >= CMP_CTAS) {
        // ---------------- COPY ROLE: warp-per-row, 8 rows/iter --------------
        const int lane = tid & 31;
        const int gw   = (blockIdx.x - CMP_CTAS) * 4 + (tid >> 5);  // 0..767
        int row = gw * ROWS_PER_IT;
#pragma unroll 1
        for (int it = 0; it < COPY_ITERS; it++) {
            float v[ROWS_PER_IT][8];
#pragma unroll
            for (int r = 0; r < ROWS_PER_IT; r++) {
                const float* src = queues + (size_t)(row + r) * TQ + lane;
#pragma unroll
                for (int k = 0; k < 8; k++)
                    v[r][k] = __ldcs(src + k * 32);
            }
#pragma unroll
            for (int r = 0; r < ROWS_PER_IT; r++) {
                float* dst = nq + (size_t)(row + r) * TQO + lane;
#pragma unroll
                for (int k = 0; k < 8; k++)
                    __stcs(dst + k * 32, v[r][k]);
            }
            row += COPY_WARPS * ROWS_PER_IT;
        }
        return;
    }

    // ---------------- COMPUTE ROLE (R11/R13 pipeline, unchanged) -----------
    const int w    = tid >> 5;
    const int lane = tid & 31;
    const int b    = blockIdx.x * 4 + w;

    const unsigned int smem_u32 = (unsigned int)__cvta_generic_to_shared(sm);

    float* s_tap = sm + ACT_OFF       + w * 32;
    float* s_cur = sm + ACT_OFF + 128 + w * 32;
    float* s_g   = sm + ACT_OFF + 256 + w * 32;

    auto issue_stage = [&](int blk, int beta) {
#pragma unroll
        for (int j = 0; j < 8; j++) {
            const int m = tid + j * 128;          // 0..1023
            const int o = m >> 4, ch = m & 15;
            cpa16(smem_u32 + (WC_OFF + beta * 4096 + SWZ16(o, ch)) * 4,
                  W_conv + (size_t)blk * 4096 + m * 4);
        }
#pragma unroll
        for (int j = 0; j < 2; j++) {
            const int m = tid + j * 128;          // 0..255
            const int o = m >> 3, ch = m & 7;
            cpa16(smem_u32 + (WRS_OFF + beta * 1024 + SWZ8(o, ch)) * 4,
                  W_res + (size_t)blk * 1024 + m * 4);
            cpa16(smem_u32 + (WSK_OFF + beta * 1024 + SWZ8(o, ch)) * 4,
                  W_skip + (size_t)blk * 1024 + m * 4);
        }
#pragma unroll
        for (int j = 0; j < 8; j++) {
            const int m = tid + j * 128;          // 0..1023
            const int h = m >> 3, ch = m & 7;
            cpa16(smem_u32 + (WO1_OFF + beta * 4096 + SWZ8(h, ch)) * 4,
                  W_o1 + (size_t)h * 768 + blk * 32 + ch * 4);
        }
        cpa_commit();
    };

    issue_stage(0, 0);

    float zb0  = b_conv[lane];
    float zb1  = b_conv[32 + lane];
    float rb   = b_res [lane];
    float sb   = b_skip[lane];
    float tapc = queues[((size_t)b * CH + lane) * TQ + (TQ - 1)];

    if (lane < 25) {
        float v;
        if (lane == 0)      v = x[b];
        else if (lane < 9)  v = num[b * 8 + (lane - 1)];
        else                v = emb[cat[b] * 16 + (lane - 9)];
        s_g[lane] = v;
    }
    __syncwarp();
    float cur = b_in[lane];
#pragma unroll
    for (int k = 0; k < 25; k++)
        cur += W_in[lane * 25 + k] * s_g[k];
    __syncwarp();

    float acc0 = 0.f, acc1 = 0.f, acc2 = 0.f, acc3 = 0.f;

#pragma unroll 1
    for (int i = 0; i < NBLK; i++) {
        const int alpha = i & 1;

        cpa_wait0();
        __syncthreads();

        if (i < NBLK - 1)
            issue_stage(i + 1, alpha ^ 1);

        float zb0n, zb1n, rbn, sbn, tapn;
        if (i < NBLK - 1) {
            const int in = i + 1;
            zb0n = b_conv[in * 64 + lane];
            zb1n = b_conv[in * 64 + 32 + lane];
            rbn  = b_res [in * 32 + lane];
            sbn  = b_skip[in * 32 + lane];
            const int dn = 1 << (in & 7);
            tapn = queues[((size_t)(in * BATCH + b) * CH + lane) * TQ + (TQ - dn)];
        }

        const size_t rowbase = (size_t)(i * BATCH + b) * CH + lane;
        nq[rowbase * TQO + TQ] = cur;
        s_tap[lane] = tapc;
        s_cur[lane] = cur;
        __syncwarp();

        const float* wc  = sm + WC_OFF  + alpha * 4096;
        const float* wrs = sm + WRS_OFF + alpha * 1024;
        const float* wsk = sm + WSK_OFF + alpha * 1024;
        const float* wo1 = sm + WO1_OFF + alpha * 4096;

        float z0a = zb0, z0b = 0.f, z1a = zb1, z1b = 0.f;
#pragma unroll
        for (int q = 0; q < 8; q++) {
            const float4 a  = *(const float4*)&s_tap[4 * q];
            const float4 u  = *(const float4*)&s_cur[4 * q];
            const float4 f00 = *(const float4*)&wc[SWZ16(lane,      2 * q    )];
            const float4 f01 = *(const float4*)&wc[SWZ16(lane,      2 * q + 1)];
            const float4 f10 = *(const float4*)&wc[SWZ16(lane + 32, 2 * q    )];
            const float4 f11 = *(const float4*)&wc[SWZ16(lane + 32, 2 * q + 1)];
            z0a += a.x * f00.x + a.y * f00.z;
            z0b += u.x * f00.y + u.y * f00.w;
            z0a += a.z * f01.x + a.w * f01.z;
            z0b += u.z * f01.y + u.w * f01.w;
            z1a += a.x * f10.x + a.y * f10.z;
            z1b += u.x * f10.y + u.y * f10.w;
            z1a += a.z * f11.x + a.w * f11.z;
            z1b += u.z * f11.y + u.w * f11.w;
        }

        const float z1s = z1a + z1b;
        const float gated = tanhf(z0a + z0b) * (1.f / (1.f + __expf(-z1s)));
        s_g[lane] = gated;
        __syncwarp();

        float sk = sb, rs = rb;
#pragma unroll
        for (int q = 0; q < 8; q++) {
            const float4 g  = *(const float4*)&s_g[4 * q];
            const float4 wr = *(const float4*)&wrs[SWZ8(lane, q)];
            const float4 ws = *(const float4*)&wsk[SWZ8(lane, q)];
            rs += g.x * wr.x + g.y * wr.y + g.z * wr.z + g.w * wr.w;
            sk += g.x * ws.x + g.y * ws.y + g.z * ws.z + g.w * ws.w;
        }
        cur = rs + cur;

        s_tap[lane] = fmaxf(sk, 0.f);
        __syncwarp();

#pragma unroll
        for (int q = 0; q < 8; q++) {
            const float4 sr = *(const float4*)&s_tap[4 * q];
            const float4 v0 = *(const float4*)&wo1[SWZ8(lane,      q)];
            const float4 v1 = *(const float4*)&wo1[SWZ8(lane + 32, q)];
            const float4 v2 = *(const float4*)&wo1[SWZ8(lane + 64, q)];
            const float4 v3 = *(const float4*)&wo1[SWZ8(lane + 96, q)];
            acc0 += sr.x * v0.x + sr.y * v0.y + sr.z * v0.z + sr.w * v0.w;
            acc1 += sr.x * v1.x + sr.y * v1.y + sr.z * v1.z + sr.w * v1.w;
            acc2 += sr.x * v2.x + sr.y * v2.y + sr.z * v2.z + sr.w * v2.w;
            acc3 += sr.x * v3.x + sr.y * v3.y + sr.z * v3.z + sr.w * v3.w;
        }

        if (i < NBLK - 1) {
            zb0 = zb0n; zb1 = zb1n; rb = rbn; sb = sbn; tapc = tapn;
        }
        __syncthreads();
    }

    float p = 0.f;
    p += fmaxf(acc0 + b_o1[lane      ], 0.f) * W_o2[lane      ];
    p += fmaxf(acc1 + b_o1[lane + 32 ], 0.f) * W_o2[lane + 32 ];
    p += fmaxf(acc2 + b_o1[lane + 64 ], 0.f) * W_o2[lane + 64 ];
    p += fmaxf(acc3 + b_o1[lane + 96 ], 0.f) * W_o2[lane + 96 ];
#pragma unroll
    for (int off = 16; off; off >>= 1)
        p += __shfl_xor_sync(0xffffffffu, p, off);
    if (lane == 0)
        out[b] = p + b_o2[0];
}

extern "C" void kernel_launch(void* const* d_in, const int* in_sizes, int n_in,
                              void* d_out, int out_size) {
    const float* queues = (const float*)d_in[0];
    const float* x      = (const float*)d_in[1];
    const float* num    = (const float*)d_in[2];
    const int*   cat    = (const int*)  d_in[3];
    const float* emb    = (const float*)d_in[4];
    const float* W_in   = (const float*)d_in[5];
    const float* b_in   = (const float*)d_in[6];
    const float* W_conv = (const float*)d_in[7];
    const float* b_conv = (const float*)d_in[8];
    const float* W_res  = (const float*)d_in[9];
    const float* b_res  = (const float*)d_in[10];
    const float* W_skip = (const float*)d_in[11];
    const float* b_skip = (const float*)d_in[12];
    const float* W_o1   = (const float*)d_in[13];
    const float* b_o1   = (const float*)d_in[14];
    const float* W_o2   = (const float*)d_in[15];
    const float* b_o2   = (const float*)d_in[16];
    float* out = (float*)d_out;

    static bool configured = false;
    if (!configured) {
        configured = true;
        cudaFuncSetAttribute(wave_fused_kernel,
                             cudaFuncAttributeMaxDynamicSharedMemorySize,
                             SMEM_BYTES);
    }

    wave_fused_kernel<<<CMP_CTAS + COPY_CTAS, TPB, SMEM_BYTES>>>(
        queues, x, num, cat, emb, W_in, b_in, W_conv, b_conv,
        W_res, b_res, W_skip, b_skip, W_o1, b_o1, W_o2, b_o2, out);
}